// round 1
// baseline (speedup 1.0000x reference)
#include <cuda_runtime.h>
#include <math.h>

// ---------------- scratch (device globals; no allocation allowed) ----------
__device__ float g_bufA[33554432];   // conv1 out (8,64,256,256) / pooled (8,128,128,128)
__device__ float g_bufB[67108864];   // conv2 out (8,128,256,256)
__device__ float g_bufC[33554432];   // conv3 out (8,256,128,128)
__device__ float g_bufD[33554432];   // conv4 out for sr pass (8,256,128,128)
__device__ double g_acc[3];          // 0: mse sum, 1: ssim S sum, 2: perceptual sum

__global__ void zero_acc_kernel() {
    g_acc[0] = 0.0; g_acc[1] = 0.0; g_acc[2] = 0.0;
}

// ---------------- block reduce helper ----------------
__device__ __forceinline__ float block_reduce_sum(float v, float* sh, int tid) {
    #pragma unroll
    for (int o = 16; o > 0; o >>= 1) v += __shfl_down_sync(0xffffffffu, v, o);
    if ((tid & 31) == 0) sh[tid >> 5] = v;
    __syncthreads();
    if (tid < 32) {
        v = (tid < 8) ? sh[tid] : 0.0f;   // 256 threads -> 8 warps
        #pragma unroll
        for (int o = 4; o > 0; o >>= 1) v += __shfl_down_sync(0xffffffffu, v, o);
    }
    return v;  // valid in tid 0
}

// ---------------- MSE ----------------
__global__ void mse_kernel(const float* __restrict__ a, const float* __restrict__ b, int n) {
    __shared__ float sh[32];
    float s = 0.0f;
    for (int i = blockIdx.x * blockDim.x + threadIdx.x; i < n; i += gridDim.x * blockDim.x) {
        float d = a[i] - b[i];
        s = fmaf(d, d, s);
    }
    s = block_reduce_sum(s, sh, threadIdx.x);
    if (threadIdx.x == 0) atomicAdd(&g_acc[0], (double)s);
}

// ---------------- SSIM (7x7 valid box filter, skimage formula) -------------
__global__ void ssim_kernel(const float* __restrict__ x, const float* __restrict__ y) {
    // grid (16,16,8), block (16,16); output 250x250 per image
    __shared__ float sxt[22][23];
    __shared__ float syt[22][23];
    __shared__ float sh[32];
    int b = blockIdx.z;
    int gx0 = blockIdx.x * 16, gy0 = blockIdx.y * 16;
    const float* xb = x + (size_t)b * 65536;
    const float* yb = y + (size_t)b * 65536;
    int tid = threadIdx.y * 16 + threadIdx.x;
    for (int i = tid; i < 22 * 22; i += 256) {
        int rr = i / 22, cc = i - rr * 22;
        int gy = gy0 + rr, gx = gx0 + cc;
        float vx = 0.0f, vy = 0.0f;
        if (gy < 256 && gx < 256) { vx = xb[gy * 256 + gx]; vy = yb[gy * 256 + gx]; }
        sxt[rr][cc] = vx; syt[rr][cc] = vy;
    }
    __syncthreads();
    int i = gy0 + threadIdx.y, j = gx0 + threadIdx.x;
    float S = 0.0f;
    if (i < 250 && j < 250) {
        float sx = 0, sy = 0, sxx = 0, syy = 0, sxy = 0;
        #pragma unroll
        for (int dy = 0; dy < 7; dy++) {
            #pragma unroll
            for (int dx = 0; dx < 7; dx++) {
                float a = sxt[threadIdx.y + dy][threadIdx.x + dx];
                float c = syt[threadIdx.y + dy][threadIdx.x + dx];
                sx += a; sy += c;
                sxx = fmaf(a, a, sxx); syy = fmaf(c, c, syy); sxy = fmaf(a, c, sxy);
            }
        }
        const float inv = 1.0f / 49.0f;
        const float cn  = 49.0f / 48.0f;
        float ux = sx * inv, uy = sy * inv;
        float vx  = cn * (sxx * inv - ux * ux);
        float vy  = cn * (syy * inv - uy * uy);
        float vxy = cn * (sxy * inv - ux * uy);
        const float C1 = 1e-4f, C2 = 9e-4f;
        S = ((2.0f * ux * uy + C1) * (2.0f * vxy + C2)) /
            ((ux * ux + uy * uy + C1) * (vx + vy + C2));
    }
    float tot = block_reduce_sum(S, sh, tid);
    if (tid == 0) atomicAdd(&g_acc[1], (double)tot);
}

// ---------------- conv1: 1 -> 64 channels, 256x256 SAME, relu --------------
__global__ void conv1_kernel(const float* __restrict__ in, const float* __restrict__ w,
                             const float* __restrict__ bias, float* __restrict__ out) {
    __shared__ float sw[576];
    __shared__ float sb[64];
    int tid = threadIdx.x;
    for (int i = tid; i < 576; i += 256) sw[i] = w[i];
    if (tid < 64) sb[tid] = bias[tid];
    __syncthreads();
    int g = blockIdx.x * 256 + tid;         // 8*256*64 threads total
    int x4 = (g & 63) * 4;
    int y  = (g >> 6) & 255;
    int b  = g >> 14;
    const float* ib = in + (size_t)b * 65536;
    float inp[3][6];
    #pragma unroll
    for (int dy = 0; dy < 3; dy++) {
        int gy = y - 1 + dy;
        #pragma unroll
        for (int c = 0; c < 6; c++) {
            int gx = x4 - 1 + c;
            inp[dy][c] = ((unsigned)gy < 256u && (unsigned)gx < 256u) ? ib[gy * 256 + gx] : 0.0f;
        }
    }
    for (int co = 0; co < 64; co++) {
        float bv = sb[co];
        float a0 = bv, a1 = bv, a2 = bv, a3 = bv;
        #pragma unroll
        for (int k = 0; k < 9; k++) {
            float wv = sw[co * 9 + k];
            int ky = k / 3, kx = k - ky * 3;
            a0 = fmaf(inp[ky][0 + kx], wv, a0);
            a1 = fmaf(inp[ky][1 + kx], wv, a1);
            a2 = fmaf(inp[ky][2 + kx], wv, a2);
            a3 = fmaf(inp[ky][3 + kx], wv, a3);
        }
        float4 v = make_float4(fmaxf(a0, 0.0f), fmaxf(a1, 0.0f), fmaxf(a2, 0.0f), fmaxf(a3, 0.0f));
        *(float4*)(out + ((size_t)(b * 64 + co) * 65536) + (size_t)y * 256 + x4) = v;
    }
}

// ---------------- maxpool 2x2 stride 2 ----------------
__global__ void pool_kernel(const float* __restrict__ in, float* __restrict__ out,
                            int C, int Ho, int Wo) {
    int n = 8 * C * Ho * Wo;
    int Wi = 2 * Wo;
    for (int i = blockIdx.x * blockDim.x + threadIdx.x; i < n; i += gridDim.x * blockDim.x) {
        int x = i % Wo;
        int y = (i / Wo) % Ho;
        int bc = i / (Wo * Ho);
        const float* p = in + ((size_t)bc * 2 * Ho + 2 * y) * Wi + 2 * x;
        float m = fmaxf(fmaxf(p[0], p[1]), fmaxf(p[Wi], p[Wi + 1]));
        out[i] = m;
    }
}

// ---------------- generic 3x3 SAME conv + relu (Cin % 8 == 0) --------------
// Block tile: 64(x) x 8(y) pixels x 32 output channels, one image.
// Thread: 8 consecutive x-pixels x 8 output channels.
// mode 0: out = relu(conv);  mode 1: accumulate sum((relu(conv) - ref)^2) into g_acc[2]
#define CK 8
__global__ __launch_bounds__(256, 2) void conv_main(
    const float* __restrict__ in, const float* __restrict__ w, const float* __restrict__ bias,
    float* __restrict__ out, const float* __restrict__ ref,
    int Cin, int Cout, int H, int W, int mode)
{
    __shared__ float s_in[CK][10][66];
    __shared__ float s_w[32][CK][9];
    __shared__ float s_red[32];

    int tid = threadIdx.x;
    int pg = tid & 7;
    int r  = (tid >> 3) & 7;
    int cg = tid >> 6;
    int bx = blockIdx.x, by = blockIdx.y;
    int cbn = Cout >> 5;
    int cb = blockIdx.z % cbn;
    int b  = blockIdx.z / cbn;
    int x0 = bx * 64 + pg * 8;
    int y  = by * 8 + r;
    int co0 = cb * 32 + cg * 8;

    float acc[8][8];
    #pragma unroll
    for (int j = 0; j < 8; j++)
        #pragma unroll
        for (int px = 0; px < 8; px++) acc[j][px] = 0.0f;

    const float* inb = in + (size_t)b * Cin * H * W;
    for (int ci0 = 0; ci0 < Cin; ci0 += CK) {
        // stage input tile: CK channels x 10 rows x 66 cols (with zero padding)
        for (int i = tid; i < CK * 10 * 66; i += 256) {
            int ci = i / 660;
            int rem = i - ci * 660;
            int rr = rem / 66;
            int cc = rem - rr * 66;
            int gy = by * 8 - 1 + rr;
            int gx = bx * 64 - 1 + cc;
            float v = 0.0f;
            if ((unsigned)gy < (unsigned)H && (unsigned)gx < (unsigned)W)
                v = inb[(size_t)(ci0 + ci) * H * W + (size_t)gy * W + gx];
            s_in[ci][rr][cc] = v;
        }
        // stage weights: 32 co x CK ci x 9
        for (int i = tid; i < 32 * CK * 9; i += 256) {
            int co = i / (CK * 9);
            int rem = i - co * CK * 9;
            int ci = rem / 9;
            int k  = rem - ci * 9;
            s_w[co][ci][k] = w[((size_t)(cb * 32 + co) * Cin + (ci0 + ci)) * 9 + k];
        }
        __syncthreads();

        #pragma unroll
        for (int ci = 0; ci < CK; ci++) {
            float inp[3][10];
            #pragma unroll
            for (int dy = 0; dy < 3; dy++)
                #pragma unroll
                for (int c = 0; c < 10; c++)
                    inp[dy][c] = s_in[ci][r + dy][pg * 8 + c];
            #pragma unroll
            for (int j = 0; j < 8; j++) {
                #pragma unroll
                for (int ky = 0; ky < 3; ky++) {
                    #pragma unroll
                    for (int kx = 0; kx < 3; kx++) {
                        float wv = s_w[cg * 8 + j][ci][ky * 3 + kx];
                        #pragma unroll
                        for (int px = 0; px < 8; px++)
                            acc[j][px] = fmaf(inp[ky][px + kx], wv, acc[j][px]);
                    }
                }
            }
        }
        __syncthreads();
    }

    if (mode == 0) {
        #pragma unroll
        for (int j = 0; j < 8; j++) {
            float bv = __ldg(&bias[co0 + j]);
            size_t base = ((size_t)(b * Cout + co0 + j) * H + y) * W + x0;
            float4 v0, v1;
            v0.x = fmaxf(acc[j][0] + bv, 0.0f);
            v0.y = fmaxf(acc[j][1] + bv, 0.0f);
            v0.z = fmaxf(acc[j][2] + bv, 0.0f);
            v0.w = fmaxf(acc[j][3] + bv, 0.0f);
            v1.x = fmaxf(acc[j][4] + bv, 0.0f);
            v1.y = fmaxf(acc[j][5] + bv, 0.0f);
            v1.z = fmaxf(acc[j][6] + bv, 0.0f);
            v1.w = fmaxf(acc[j][7] + bv, 0.0f);
            *(float4*)(out + base)     = v0;
            *(float4*)(out + base + 4) = v1;
        }
    } else {
        float lsum = 0.0f;
        #pragma unroll
        for (int j = 0; j < 8; j++) {
            float bv = __ldg(&bias[co0 + j]);
            size_t base = ((size_t)(b * Cout + co0 + j) * H + y) * W + x0;
            #pragma unroll
            for (int px = 0; px < 8; px++) {
                float v = fmaxf(acc[j][px] + bv, 0.0f);
                float d = v - ref[base + px];
                lsum = fmaf(d, d, lsum);
            }
        }
        float tot = block_reduce_sum(lsum, s_red, tid);
        if (tid == 0) atomicAdd(&g_acc[2], (double)tot);
    }
}

// ---------------- finalize ----------------
__global__ void finalize_kernel(float* out, int out_size) {
    double mse    = g_acc[0] / 524288.0;                 // 8*1*256*256
    double ssim_l = 1.0 - g_acc[1] / 500000.0;           // 8*250*250
    double perc   = g_acc[2] / 33554432.0;               // 8*256*128*128
    double total  = mse + 0.5 * ssim_l + 0.1 * perc;
    float vals[4] = {(float)total, (float)mse, (float)ssim_l, (float)perc};
    for (int i = 0; i < 4 && i < out_size; i++) out[i] = vals[i];
}

// ---------------- launcher ----------------
extern "C" void kernel_launch(void* const* d_in, const int* in_sizes, int n_in,
                              void* d_out, int out_size) {
    (void)in_sizes; (void)n_in;
    const float* sr = (const float*)d_in[0];
    const float* hr = (const float*)d_in[1];
    const float* w1 = (const float*)d_in[2];
    const float* b1 = (const float*)d_in[3];
    const float* w2 = (const float*)d_in[4];
    const float* b2 = (const float*)d_in[5];
    const float* w3 = (const float*)d_in[6];
    const float* b3 = (const float*)d_in[7];
    const float* w4 = (const float*)d_in[8];
    const float* b4 = (const float*)d_in[9];
    float* out = (float*)d_out;

    float *A, *B, *C, *D;
    cudaGetSymbolAddress((void**)&A, g_bufA);
    cudaGetSymbolAddress((void**)&B, g_bufB);
    cudaGetSymbolAddress((void**)&C, g_bufC);
    cudaGetSymbolAddress((void**)&D, g_bufD);

    zero_acc_kernel<<<1, 1>>>();
    mse_kernel<<<512, 256>>>(sr, hr, 524288);
    ssim_kernel<<<dim3(16, 16, 8), dim3(16, 16)>>>(sr, hr);

    for (int pass = 0; pass < 2; pass++) {
        const float* img = pass ? hr : sr;
        // conv1: (8,1,256,256) -> A (8,64,256,256)
        conv1_kernel<<<512, 256>>>(img, w1, b1, A);
        // conv2: A -> B (8,128,256,256)
        conv_main<<<dim3(4, 32, 8 * 4), 256>>>(A, w2, b2, B, nullptr, 64, 128, 256, 256, 0);
        // pool: B -> A (8,128,128,128)
        pool_kernel<<<8192, 256>>>(B, A, 128, 128, 128);
        // conv3: A -> C (8,256,128,128)
        conv_main<<<dim3(2, 16, 8 * 8), 256>>>(A, w3, b3, C, nullptr, 128, 256, 128, 128, 0);
        // conv4: C -> D (store on sr pass) or diff-reduce vs D (hr pass)
        if (pass == 0)
            conv_main<<<dim3(2, 16, 8 * 8), 256>>>(C, w4, b4, D, nullptr, 256, 256, 128, 128, 0);
        else
            conv_main<<<dim3(2, 16, 8 * 8), 256>>>(C, w4, b4, nullptr, D, 256, 256, 128, 128, 1);
    }

    finalize_kernel<<<1, 1>>>(out, out_size);
}

// round 2
// speedup vs baseline: 1.5550x; 1.5550x over previous
#include <cuda_runtime.h>
#include <math.h>

// ---------------- scratch (device globals; no allocation allowed) ----------
__device__ float g_bufA[33554432];   // conv1 out (8,64,256,256) / pooled (8,128,128,128)
__device__ float g_bufB[67108864];   // conv2 out (8,128,256,256)
__device__ float g_bufC[33554432];   // conv3 out (8,256,128,128)
__device__ float g_bufD[33554432];   // conv4 out for sr pass (8,256,128,128)
__device__ double g_acc[3];          // 0: mse sum, 1: ssim S sum, 2: perceptual sum

__global__ void zero_acc_kernel() {
    g_acc[0] = 0.0; g_acc[1] = 0.0; g_acc[2] = 0.0;
}

// ---------------- helpers ----------------
__device__ __forceinline__ float block_reduce_sum(float v, float* sh, int tid) {
    #pragma unroll
    for (int o = 16; o > 0; o >>= 1) v += __shfl_down_sync(0xffffffffu, v, o);
    if ((tid & 31) == 0) sh[tid >> 5] = v;
    __syncthreads();
    if (tid < 32) {
        v = (tid < 8) ? sh[tid] : 0.0f;   // 256 threads -> 8 warps
        #pragma unroll
        for (int o = 4; o > 0; o >>= 1) v += __shfl_down_sync(0xffffffffu, v, o);
    }
    return v;  // valid in tid 0
}

__device__ __forceinline__ float to_tf32(float x) {
    asm("cvt.rna.tf32.f32 %0, %0;" : "+f"(x));
    return x;
}

__device__ __forceinline__ void mma_tf32(float* c, const unsigned* a, const unsigned* b) {
    asm volatile(
        "mma.sync.aligned.m16n8k8.row.col.f32.tf32.tf32.f32 "
        "{%0,%1,%2,%3}, {%4,%5,%6,%7}, {%8,%9}, {%0,%1,%2,%3};"
        : "+f"(c[0]), "+f"(c[1]), "+f"(c[2]), "+f"(c[3])
        : "r"(a[0]), "r"(a[1]), "r"(a[2]), "r"(a[3]), "r"(b[0]), "r"(b[1]));
}

// ---------------- MSE ----------------
__global__ void mse_kernel(const float* __restrict__ a, const float* __restrict__ b, int n) {
    __shared__ float sh[32];
    float s = 0.0f;
    for (int i = blockIdx.x * blockDim.x + threadIdx.x; i < n; i += gridDim.x * blockDim.x) {
        float d = a[i] - b[i];
        s = fmaf(d, d, s);
    }
    s = block_reduce_sum(s, sh, threadIdx.x);
    if (threadIdx.x == 0) atomicAdd(&g_acc[0], (double)s);
}

// ---------------- SSIM (7x7 valid box filter, skimage formula) -------------
__global__ void ssim_kernel(const float* __restrict__ x, const float* __restrict__ y) {
    __shared__ float sxt[22][23];
    __shared__ float syt[22][23];
    __shared__ float sh[32];
    int b = blockIdx.z;
    int gx0 = blockIdx.x * 16, gy0 = blockIdx.y * 16;
    const float* xb = x + (size_t)b * 65536;
    const float* yb = y + (size_t)b * 65536;
    int tid = threadIdx.y * 16 + threadIdx.x;
    for (int i = tid; i < 22 * 22; i += 256) {
        int rr = i / 22, cc = i - rr * 22;
        int gy = gy0 + rr, gx = gx0 + cc;
        float vx = 0.0f, vy = 0.0f;
        if (gy < 256 && gx < 256) { vx = xb[gy * 256 + gx]; vy = yb[gy * 256 + gx]; }
        sxt[rr][cc] = vx; syt[rr][cc] = vy;
    }
    __syncthreads();
    int i = gy0 + threadIdx.y, j = gx0 + threadIdx.x;
    float S = 0.0f;
    if (i < 250 && j < 250) {
        float sx = 0, sy = 0, sxx = 0, syy = 0, sxy = 0;
        #pragma unroll
        for (int dy = 0; dy < 7; dy++) {
            #pragma unroll
            for (int dx = 0; dx < 7; dx++) {
                float a = sxt[threadIdx.y + dy][threadIdx.x + dx];
                float c = syt[threadIdx.y + dy][threadIdx.x + dx];
                sx += a; sy += c;
                sxx = fmaf(a, a, sxx); syy = fmaf(c, c, syy); sxy = fmaf(a, c, sxy);
            }
        }
        const float inv = 1.0f / 49.0f;
        const float cn  = 49.0f / 48.0f;
        float ux = sx * inv, uy = sy * inv;
        float vx  = cn * (sxx * inv - ux * ux);
        float vy  = cn * (syy * inv - uy * uy);
        float vxy = cn * (sxy * inv - ux * uy);
        const float C1 = 1e-4f, C2 = 9e-4f;
        S = ((2.0f * ux * uy + C1) * (2.0f * vxy + C2)) /
            ((ux * ux + uy * uy + C1) * (vx + vy + C2));
    }
    float tot = block_reduce_sum(S, sh, tid);
    if (tid == 0) atomicAdd(&g_acc[1], (double)tot);
}

// ---------------- conv1: 1 -> 64 channels, 256x256 SAME, relu --------------
__global__ void conv1_kernel(const float* __restrict__ in, const float* __restrict__ w,
                             const float* __restrict__ bias, float* __restrict__ out) {
    __shared__ float sw[576];
    __shared__ float sb[64];
    int tid = threadIdx.x;
    for (int i = tid; i < 576; i += 256) sw[i] = w[i];
    if (tid < 64) sb[tid] = bias[tid];
    __syncthreads();
    int g = blockIdx.x * 256 + tid;
    int x4 = (g & 63) * 4;
    int y  = (g >> 6) & 255;
    int b  = g >> 14;
    const float* ib = in + (size_t)b * 65536;
    float inp[3][6];
    #pragma unroll
    for (int dy = 0; dy < 3; dy++) {
        int gy = y - 1 + dy;
        #pragma unroll
        for (int c = 0; c < 6; c++) {
            int gx = x4 - 1 + c;
            inp[dy][c] = ((unsigned)gy < 256u && (unsigned)gx < 256u) ? ib[gy * 256 + gx] : 0.0f;
        }
    }
    for (int co = 0; co < 64; co++) {
        float bv = sb[co];
        float a0 = bv, a1 = bv, a2 = bv, a3 = bv;
        #pragma unroll
        for (int k = 0; k < 9; k++) {
            float wv = sw[co * 9 + k];
            int ky = k / 3, kx = k - ky * 3;
            a0 = fmaf(inp[ky][0 + kx], wv, a0);
            a1 = fmaf(inp[ky][1 + kx], wv, a1);
            a2 = fmaf(inp[ky][2 + kx], wv, a2);
            a3 = fmaf(inp[ky][3 + kx], wv, a3);
        }
        float4 v = make_float4(fmaxf(a0, 0.0f), fmaxf(a1, 0.0f), fmaxf(a2, 0.0f), fmaxf(a3, 0.0f));
        *(float4*)(out + ((size_t)(b * 64 + co) * 65536) + (size_t)y * 256 + x4) = v;
    }
}

// ---------------- maxpool 2x2 stride 2 ----------------
__global__ void pool_kernel(const float* __restrict__ in, float* __restrict__ out,
                            int C, int Ho, int Wo) {
    int n = 8 * C * Ho * Wo;
    int Wi = 2 * Wo;
    for (int i = blockIdx.x * blockDim.x + threadIdx.x; i < n; i += gridDim.x * blockDim.x) {
        int x = i % Wo;
        int y = (i / Wo) % Ho;
        int bc = i / (Wo * Ho);
        const float* p = in + ((size_t)bc * 2 * Ho + 2 * y) * Wi + 2 * x;
        float m = fmaxf(fmaxf(p[0], p[1]), fmaxf(p[Wi], p[Wi + 1]));
        out[i] = m;
    }
}

// ---------------- tensor-core 3x3 SAME conv (tf32 mma.sync) ----------------
// Block: 256 threads = 8 warps arranged 2(M) x 4(N).
// Block tile: 64 Cout x 256 pixels (linear strip in row-major plane).
// Warp tile : 32 Cout x 64 pixels -> 2 m16 frags x 8 n8 frags, K = 8 Cin per step.
// 3x3 handled as 9 tap-shifted K=Cin GEMMs against a shared staged input tile.
// SMEM: s_in[8ci][4rows][258] (plane stride 1032 words == 8 mod 32: conflict-free)
//       s_w [9tap][64co][12]  (ci padded 8->12: conflict-free fragment loads)
#define SIN_PLANE 1032
#define SIN_ROW   258
#define SW_TAP    768          // 64*12
#define SIN_FLOATS (8 * SIN_PLANE)            // 8256
#define SW_FLOATS  (9 * SW_TAP)               // 6912
#define SMEM_FLOATS (SIN_FLOATS + SW_FLOATS)  // 15168 floats = 60672 B

__global__ __launch_bounds__(256) void conv_mma(
    const float* __restrict__ in, const float* __restrict__ w, const float* __restrict__ bias,
    float* __restrict__ out, const float* __restrict__ ref,
    int Cin, int Cout, int H, int W, int lw, int mode)
{
    extern __shared__ float smem[];
    float* s_in = smem;
    float* s_w  = smem + SIN_FLOATS;
    __shared__ float s_red[32];

    int tid = threadIdx.x;
    int warp = tid >> 5;
    int lane = tid & 31;
    int q  = lane >> 2;     // 0..7
    int k4 = lane & 3;      // 0..3
    int mw = warp & 1;      // M half
    int nw = warp >> 1;     // N quarter
    int mwoff = mw * 32;
    int nwoff = nw * 64;

    int HW = H * W;
    int P0 = blockIdx.x * 256;             // pixel base within plane
    int co0 = blockIdx.y * 64;
    int b   = blockIdx.z;
    int y0  = P0 >> lw;
    int wm1 = W - 1;
    int nrows = 256 >> lw;                 // 1 (W=256) or 2 (W=128)
    int srows = nrows + 2;
    int scols = W + 2;
    int stot  = 8 * srows * scols;

    float acc[2][8][4];
    #pragma unroll
    for (int f = 0; f < 2; f++)
        #pragma unroll
        for (int nf = 0; nf < 8; nf++)
            #pragma unroll
            for (int e = 0; e < 4; e++) acc[f][nf][e] = 0.0f;

    const float* inb = in + (size_t)b * Cin * HW;

    for (int ci0 = 0; ci0 < Cin; ci0 += 8) {
        __syncthreads();
        // stage input tile (tf32-rounded)
        for (int i = tid; i < stot; i += 256) {
            int ci  = i / (srows * scols);
            int rem = i - ci * (srows * scols);
            int r   = rem / scols;
            int c   = rem - r * scols;
            int gy = y0 - 1 + r;
            int gx = c - 1;
            float v = 0.0f;
            if ((unsigned)gy < (unsigned)H && (unsigned)gx < (unsigned)W)
                v = inb[(size_t)(ci0 + ci) * HW + (size_t)gy * W + gx];
            s_in[ci * SIN_PLANE + r * SIN_ROW + c] = to_tf32(v);
        }
        // stage weights: 64 co x 8 ci x 9 taps
        for (int i = tid; i < 64 * 8 * 9; i += 256) {
            int tap = i % 9;
            int t2  = i / 9;
            int ci  = t2 & 7;
            int co  = t2 >> 3;
            float v = w[((size_t)(co0 + co) * Cin + (ci0 + ci)) * 9 + tap];
            s_w[tap * SW_TAP + co * 12 + ci] = to_tf32(v);
        }
        __syncthreads();

        #pragma unroll
        for (int tap = 0; tap < 9; tap++) {
            const int ky = tap / 3, kx = tap - ky * 3;
            unsigned a[2][4];
            int wb = tap * SW_TAP + (mwoff + q) * 12 + k4;
            #pragma unroll
            for (int f = 0; f < 2; f++) {
                a[f][0] = __float_as_uint(s_w[wb + f * 192]);
                a[f][1] = __float_as_uint(s_w[wb + f * 192 + 96]);
                a[f][2] = __float_as_uint(s_w[wb + f * 192 + 4]);
                a[f][3] = __float_as_uint(s_w[wb + f * 192 + 100]);
            }
            #pragma unroll
            for (int nf = 0; nf < 8; nf++) {
                int base = nwoff + nf * 8;
                int ry   = base >> lw;
                int col  = (base & wm1) + q;
                int word = k4 * SIN_PLANE + (ry + ky) * SIN_ROW + col + kx;
                unsigned bfr[2];
                bfr[0] = __float_as_uint(s_in[word]);
                bfr[1] = __float_as_uint(s_in[word + 4 * SIN_PLANE]);
                mma_tf32(acc[0][nf], a[0], bfr);
                mma_tf32(acc[1][nf], a[1], bfr);
            }
        }
    }

    // epilogue
    if (mode == 0) {
        #pragma unroll
        for (int f = 0; f < 2; f++) {
            int coA = co0 + mwoff + f * 16 + q;
            float bv0 = __ldg(&bias[coA]);
            float bv8 = __ldg(&bias[coA + 8]);
            float* pl0 = out + (size_t)(b * Cout + coA) * HW + P0;
            float* pl8 = pl0 + (size_t)8 * HW;
            #pragma unroll
            for (int nf = 0; nf < 8; nf++) {
                int np = nwoff + nf * 8 + 2 * k4;
                float2 v0, v8;
                v0.x = fmaxf(acc[f][nf][0] + bv0, 0.0f);
                v0.y = fmaxf(acc[f][nf][1] + bv0, 0.0f);
                v8.x = fmaxf(acc[f][nf][2] + bv8, 0.0f);
                v8.y = fmaxf(acc[f][nf][3] + bv8, 0.0f);
                *(float2*)(pl0 + np) = v0;
                *(float2*)(pl8 + np) = v8;
            }
        }
    } else {
        float lsum = 0.0f;
        #pragma unroll
        for (int f = 0; f < 2; f++) {
            int coA = co0 + mwoff + f * 16 + q;
            float bv0 = __ldg(&bias[coA]);
            float bv8 = __ldg(&bias[coA + 8]);
            const float* pl0 = ref + (size_t)(b * Cout + coA) * HW + P0;
            const float* pl8 = pl0 + (size_t)8 * HW;
            #pragma unroll
            for (int nf = 0; nf < 8; nf++) {
                int np = nwoff + nf * 8 + 2 * k4;
                float d0 = fmaxf(acc[f][nf][0] + bv0, 0.0f) - pl0[np];
                float d1 = fmaxf(acc[f][nf][1] + bv0, 0.0f) - pl0[np + 1];
                float d2 = fmaxf(acc[f][nf][2] + bv8, 0.0f) - pl8[np];
                float d3 = fmaxf(acc[f][nf][3] + bv8, 0.0f) - pl8[np + 1];
                lsum = fmaf(d0, d0, lsum);
                lsum = fmaf(d1, d1, lsum);
                lsum = fmaf(d2, d2, lsum);
                lsum = fmaf(d3, d3, lsum);
            }
        }
        float tot = block_reduce_sum(lsum, s_red, tid);
        if (tid == 0) atomicAdd(&g_acc[2], (double)tot);
    }
}

// ---------------- finalize ----------------
__global__ void finalize_kernel(float* out, int out_size) {
    double mse    = g_acc[0] / 524288.0;                 // 8*1*256*256
    double ssim_l = 1.0 - g_acc[1] / 500000.0;           // 8*250*250
    double perc   = g_acc[2] / 33554432.0;               // 8*256*128*128
    double total  = mse + 0.5 * ssim_l + 0.1 * perc;
    float vals[4] = {(float)total, (float)mse, (float)ssim_l, (float)perc};
    for (int i = 0; i < 4 && i < out_size; i++) out[i] = vals[i];
}

// ---------------- launcher ----------------
extern "C" void kernel_launch(void* const* d_in, const int* in_sizes, int n_in,
                              void* d_out, int out_size) {
    (void)in_sizes; (void)n_in;
    const float* sr = (const float*)d_in[0];
    const float* hr = (const float*)d_in[1];
    const float* w1 = (const float*)d_in[2];
    const float* b1 = (const float*)d_in[3];
    const float* w2 = (const float*)d_in[4];
    const float* b2 = (const float*)d_in[5];
    const float* w3 = (const float*)d_in[6];
    const float* b3 = (const float*)d_in[7];
    const float* w4 = (const float*)d_in[8];
    const float* b4 = (const float*)d_in[9];
    float* out = (float*)d_out;

    float *A, *B, *C, *D;
    cudaGetSymbolAddress((void**)&A, g_bufA);
    cudaGetSymbolAddress((void**)&B, g_bufB);
    cudaGetSymbolAddress((void**)&C, g_bufC);
    cudaGetSymbolAddress((void**)&D, g_bufD);

    const int smem_bytes = SMEM_FLOATS * sizeof(float);   // 60672
    cudaFuncSetAttribute(conv_mma, cudaFuncAttributeMaxDynamicSharedMemorySize, smem_bytes);

    zero_acc_kernel<<<1, 1>>>();
    mse_kernel<<<512, 256>>>(sr, hr, 524288);
    ssim_kernel<<<dim3(16, 16, 8), dim3(16, 16)>>>(sr, hr);

    for (int pass = 0; pass < 2; pass++) {
        const float* img = pass ? hr : sr;
        // conv1: (8,1,256,256) -> A (8,64,256,256)
        conv1_kernel<<<512, 256>>>(img, w1, b1, A);
        // conv2: A -> B (8,128,256,256)
        conv_mma<<<dim3(256, 2, 8), 256, smem_bytes>>>(A, w2, b2, B, nullptr,
                                                       64, 128, 256, 256, 8, 0);
        // pool: B -> A (8,128,128,128)
        pool_kernel<<<8192, 256>>>(B, A, 128, 128, 128);
        // conv3: A -> C (8,256,128,128)
        conv_mma<<<dim3(64, 4, 8), 256, smem_bytes>>>(A, w3, b3, C, nullptr,
                                                      128, 256, 128, 128, 7, 0);
        // conv4: C -> D (store on sr pass) or diff-reduce vs D (hr pass)
        if (pass == 0)
            conv_mma<<<dim3(64, 4, 8), 256, smem_bytes>>>(C, w4, b4, D, nullptr,
                                                          256, 256, 128, 128, 7, 0);
        else
            conv_mma<<<dim3(64, 4, 8), 256, smem_bytes>>>(C, w4, b4, nullptr, D,
                                                          256, 256, 128, 128, 7, 1);
    }

    finalize_kernel<<<1, 1>>>(out, out_size);
}

// round 3
// speedup vs baseline: 3.9109x; 2.5152x over previous
#include <cuda_runtime.h>
#include <math.h>

// ---------------- scratch (device globals; no allocation allowed) ----------
__device__ float g_bufA[33554432];   // conv1 out (8,64,256,256) / pooled (8,128,128,128)
__device__ float g_bufB[67108864];   // conv2 out (8,128,256,256)
__device__ float g_bufC[33554432];   // conv3 out (8,256,128,128)
__device__ float g_bufD[33554432];   // conv4 out for sr pass (8,256,128,128)
__device__ double g_acc[3];          // 0: mse sum, 1: ssim S sum, 2: perceptual sum

__global__ void zero_acc_kernel() {
    g_acc[0] = 0.0; g_acc[1] = 0.0; g_acc[2] = 0.0;
}

// ---------------- helpers ----------------
__device__ __forceinline__ float block_reduce_sum(float v, float* sh, int tid) {
    #pragma unroll
    for (int o = 16; o > 0; o >>= 1) v += __shfl_down_sync(0xffffffffu, v, o);
    if ((tid & 31) == 0) sh[tid >> 5] = v;
    __syncthreads();
    if (tid < 32) {
        v = (tid < 8) ? sh[tid] : 0.0f;   // 256 threads -> 8 warps
        #pragma unroll
        for (int o = 4; o > 0; o >>= 1) v += __shfl_down_sync(0xffffffffu, v, o);
    }
    return v;  // valid in tid 0
}

__device__ __forceinline__ float to_tf32(float x) {
    asm("cvt.rna.tf32.f32 %0, %0;" : "+f"(x));
    return x;
}

__device__ __forceinline__ void mma_tf32(float* c, const float4 a, const float2 b) {
    asm volatile(
        "mma.sync.aligned.m16n8k8.row.col.f32.tf32.tf32.f32 "
        "{%0,%1,%2,%3}, {%4,%5,%6,%7}, {%8,%9}, {%0,%1,%2,%3};"
        : "+f"(c[0]), "+f"(c[1]), "+f"(c[2]), "+f"(c[3])
        : "r"(__float_as_uint(a.x)), "r"(__float_as_uint(a.y)),
          "r"(__float_as_uint(a.z)), "r"(__float_as_uint(a.w)),
          "r"(__float_as_uint(b.x)), "r"(__float_as_uint(b.y)));
}

// ---------------- MSE ----------------
__global__ void mse_kernel(const float* __restrict__ a, const float* __restrict__ b, int n) {
    __shared__ float sh[32];
    float s = 0.0f;
    for (int i = blockIdx.x * blockDim.x + threadIdx.x; i < n; i += gridDim.x * blockDim.x) {
        float d = a[i] - b[i];
        s = fmaf(d, d, s);
    }
    s = block_reduce_sum(s, sh, threadIdx.x);
    if (threadIdx.x == 0) atomicAdd(&g_acc[0], (double)s);
}

// ---------------- SSIM (7x7 valid box filter, skimage formula) -------------
__global__ void ssim_kernel(const float* __restrict__ x, const float* __restrict__ y) {
    __shared__ float sxt[22][23];
    __shared__ float syt[22][23];
    __shared__ float sh[32];
    int b = blockIdx.z;
    int gx0 = blockIdx.x * 16, gy0 = blockIdx.y * 16;
    const float* xb = x + (size_t)b * 65536;
    const float* yb = y + (size_t)b * 65536;
    int tid = threadIdx.y * 16 + threadIdx.x;
    for (int i = tid; i < 22 * 22; i += 256) {
        int rr = i / 22, cc = i - rr * 22;
        int gy = gy0 + rr, gx = gx0 + cc;
        float vx = 0.0f, vy = 0.0f;
        if (gy < 256 && gx < 256) { vx = xb[gy * 256 + gx]; vy = yb[gy * 256 + gx]; }
        sxt[rr][cc] = vx; syt[rr][cc] = vy;
    }
    __syncthreads();
    int i = gy0 + threadIdx.y, j = gx0 + threadIdx.x;
    float S = 0.0f;
    if (i < 250 && j < 250) {
        float sx = 0, sy = 0, sxx = 0, syy = 0, sxy = 0;
        #pragma unroll
        for (int dy = 0; dy < 7; dy++) {
            #pragma unroll
            for (int dx = 0; dx < 7; dx++) {
                float a = sxt[threadIdx.y + dy][threadIdx.x + dx];
                float c = syt[threadIdx.y + dy][threadIdx.x + dx];
                sx += a; sy += c;
                sxx = fmaf(a, a, sxx); syy = fmaf(c, c, syy); sxy = fmaf(a, c, sxy);
            }
        }
        const float inv = 1.0f / 49.0f;
        const float cn  = 49.0f / 48.0f;
        float ux = sx * inv, uy = sy * inv;
        float vx  = cn * (sxx * inv - ux * ux);
        float vy  = cn * (syy * inv - uy * uy);
        float vxy = cn * (sxy * inv - ux * uy);
        const float C1 = 1e-4f, C2 = 9e-4f;
        S = ((2.0f * ux * uy + C1) * (2.0f * vxy + C2)) /
            ((ux * ux + uy * uy + C1) * (vx + vy + C2));
    }
    float tot = block_reduce_sum(S, sh, tid);
    if (tid == 0) atomicAdd(&g_acc[1], (double)tot);
}

// ---------------- conv1: 1 -> 64 channels, 256x256 SAME, relu --------------
__global__ void conv1_kernel(const float* __restrict__ in, const float* __restrict__ w,
                             const float* __restrict__ bias, float* __restrict__ out) {
    __shared__ float sw[576];
    __shared__ float sb[64];
    int tid = threadIdx.x;
    for (int i = tid; i < 576; i += 256) sw[i] = w[i];
    if (tid < 64) sb[tid] = bias[tid];
    __syncthreads();
    int g = blockIdx.x * 256 + tid;
    int x4 = (g & 63) * 4;
    int y  = (g >> 6) & 255;
    int b  = g >> 14;
    const float* ib = in + (size_t)b * 65536;
    float inp[3][6];
    #pragma unroll
    for (int dy = 0; dy < 3; dy++) {
        int gy = y - 1 + dy;
        #pragma unroll
        for (int c = 0; c < 6; c++) {
            int gx = x4 - 1 + c;
            inp[dy][c] = ((unsigned)gy < 256u && (unsigned)gx < 256u) ? ib[gy * 256 + gx] : 0.0f;
        }
    }
    for (int co = 0; co < 64; co++) {
        float bv = sb[co];
        float a0 = bv, a1 = bv, a2 = bv, a3 = bv;
        #pragma unroll
        for (int k = 0; k < 9; k++) {
            float wv = sw[co * 9 + k];
            int ky = k / 3, kx = k - ky * 3;
            a0 = fmaf(inp[ky][0 + kx], wv, a0);
            a1 = fmaf(inp[ky][1 + kx], wv, a1);
            a2 = fmaf(inp[ky][2 + kx], wv, a2);
            a3 = fmaf(inp[ky][3 + kx], wv, a3);
        }
        float4 v = make_float4(fmaxf(a0, 0.0f), fmaxf(a1, 0.0f), fmaxf(a2, 0.0f), fmaxf(a3, 0.0f));
        *(float4*)(out + ((size_t)(b * 64 + co) * 65536) + (size_t)y * 256 + x4) = v;
    }
}

// ---------------- maxpool 2x2 stride 2 ----------------
__global__ void pool_kernel(const float* __restrict__ in, float* __restrict__ out,
                            int C, int Ho, int Wo) {
    int n = 8 * C * Ho * Wo;
    int Wi = 2 * Wo;
    for (int i = blockIdx.x * blockDim.x + threadIdx.x; i < n; i += gridDim.x * blockDim.x) {
        int x = i % Wo;
        int y = (i / Wo) % Ho;
        int bc = i / (Wo * Ho);
        const float* p = in + ((size_t)bc * 2 * Ho + 2 * y) * Wi + 2 * x;
        float m = fmaxf(fmaxf(p[0], p[1]), fmaxf(p[Wi], p[Wi + 1]));
        out[i] = m;
    }
}

// ---------------- tensor-core 3x3 SAME conv (tf32 mma.sync), v2 ------------
// Templated on W (H == W). Block: 8 warps = 2(M:co) x 4(N:pixels).
// Block tile: 64 Cout x 256 pixels; warp tile 32 Cout x 64 px; K = 8 Cin/step.
// SMEM input : pixel-major, 8 channels per pixel as 4 interleaved (ci, ci+4)
//              pairs -> B fragment = one LDS.64, conflict-free.
// SMEM weight: fragment-major [tap][mw][f][q][k4][4] -> A frag = one LDS.128.
// All per-tap offsets compile-time (LDS immediate offsets).
template<int W>
__global__ __launch_bounds__(256, 2) void conv_mma(
    const float* __restrict__ in, const float* __restrict__ w, const float* __restrict__ bias,
    float* __restrict__ out, const float* __restrict__ ref,
    int Cin, int Cout, int mode)
{
    constexpr int H = W;
    constexpr int HW = W * W;
    constexpr int LW = (W == 256) ? 8 : 7;
    constexpr int NROWS = 256 / W;          // rows of pixels per 256-px strip
    constexpr int SROWS = NROWS + 2;
    constexpr int SCOLS = W + 2;
    constexpr int NPIX  = SROWS * SCOLS;
    constexpr int SIN_FLOATS = NPIX * 8;
    constexpr int SW_FLOATS  = 9 * 512;     // 9 taps x 64co x 8ci

    extern __shared__ float smem[];
    float* s_in = smem;
    float* s_w  = smem + SIN_FLOATS;
    __shared__ float s_red[32];

    int tid = threadIdx.x;
    int warp = tid >> 5;
    int lane = tid & 31;
    int q  = lane >> 2;     // 0..7
    int k4 = lane & 3;      // 0..3
    int mw = warp & 1;      // M half (co 0..31 / 32..63)
    int nw = warp >> 1;     // N quarter (64 px)
    int mwoff = mw * 32;
    int nwoff = nw * 64;

    int P0  = blockIdx.x * 256;             // pixel base within plane
    int co0 = blockIdx.y * 64;
    int b   = blockIdx.z;
    int y0  = P0 >> LW;

    // A-frag base offsets in s_w (floats), per f; tap adds tap*512
    int awb0 = (((mw * 2 + 0) * 8 + q) * 4 + k4) * 4;
    int awb1 = awb0 + 128;

    // B-frag base word offsets per nf (floats); tap adds (ky*SCOLS+kx)*8
    int bb[8];
    #pragma unroll
    for (int nf = 0; nf < 8; nf++) {
        int base = nwoff + nf * 8;
        int ry   = base >> LW;
        int col  = base & (W - 1);
        bb[nf] = (ry * SCOLS + col + q) * 8 + k4 * 2;
    }

    float acc[2][8][4];
    #pragma unroll
    for (int f = 0; f < 2; f++)
        #pragma unroll
        for (int nf = 0; nf < 8; nf++)
            #pragma unroll
            for (int e = 0; e < 4; e++) acc[f][nf][e] = 0.0f;

    const float* inb = in + (size_t)b * Cin * HW;

    for (int ci0 = 0; ci0 < Cin; ci0 += 8) {
        __syncthreads();
        // ---- stage input: (pixel, k4) -> float2 (ci=k4, ci=k4+4) ----
        for (int i = tid; i < NPIX * 4; i += 256) {
            int p = i >> 2;
            int j = i & 3;
            int r = p / SCOLS, c = p - r * SCOLS;
            int gy = y0 - 1 + r;
            int gx = c - 1;
            float v0 = 0.0f, v1 = 0.0f;
            if ((unsigned)gy < (unsigned)H && (unsigned)gx < (unsigned)W) {
                const float* src = inb + (size_t)(ci0 + j) * HW + (size_t)gy * W + gx;
                v0 = src[0];
                v1 = src[4 * HW];
            }
            float2 val;
            val.x = to_tf32(v0);
            val.y = to_tf32(v1);
            *(float2*)(s_in + p * 8 + j * 2) = val;
        }
        // ---- stage weights: fragment-major layout ----
        for (int i = tid; i < SW_FLOATS; i += 256) {
            int e   = i & 3;
            int kk  = (i >> 2) & 3;
            int qq  = (i >> 4) & 7;
            int ff  = (i >> 7) & 1;
            int mm  = (i >> 8) & 1;
            int tap = i >> 9;
            int co  = mm * 32 + ff * 16 + qq + (e & 1) * 8;
            int ci  = kk + (e >> 1) * 4;
            s_w[i] = to_tf32(w[((size_t)(co0 + co) * Cin + (ci0 + ci)) * 9 + tap]);
        }
        __syncthreads();

        #pragma unroll
        for (int tap = 0; tap < 9; tap++) {
            constexpr int dummy = 0; (void)dummy;
            const int ky = tap / 3, kx = tap - ky * 3;
            const int toff = (ky * SCOLS + kx) * 8;  // compile-time
            float4 af0 = *(const float4*)(s_w + tap * 512 + awb0);
            float4 af1 = *(const float4*)(s_w + tap * 512 + awb1);
            #pragma unroll
            for (int nf = 0; nf < 8; nf++) {
                float2 bv = *(const float2*)(s_in + bb[nf] + toff);
                mma_tf32(acc[0][nf], af0, bv);
                mma_tf32(acc[1][nf], af1, bv);
            }
        }
    }

    // ---- epilogue ----
    if (mode == 0) {
        #pragma unroll
        for (int f = 0; f < 2; f++) {
            int coA = co0 + mwoff + f * 16 + q;
            float bv0 = __ldg(&bias[coA]);
            float bv8 = __ldg(&bias[coA + 8]);
            float* pl0 = out + (size_t)(b * Cout + coA) * HW + P0;
            float* pl8 = pl0 + (size_t)8 * HW;
            #pragma unroll
            for (int nf = 0; nf < 8; nf++) {
                int np = nwoff + nf * 8 + 2 * k4;
                float2 v0, v8;
                v0.x = fmaxf(acc[f][nf][0] + bv0, 0.0f);
                v0.y = fmaxf(acc[f][nf][1] + bv0, 0.0f);
                v8.x = fmaxf(acc[f][nf][2] + bv8, 0.0f);
                v8.y = fmaxf(acc[f][nf][3] + bv8, 0.0f);
                *(float2*)(pl0 + np) = v0;
                *(float2*)(pl8 + np) = v8;
            }
        }
    } else {
        float lsum = 0.0f;
        #pragma unroll
        for (int f = 0; f < 2; f++) {
            int coA = co0 + mwoff + f * 16 + q;
            float bv0 = __ldg(&bias[coA]);
            float bv8 = __ldg(&bias[coA + 8]);
            const float* pl0 = ref + (size_t)(b * Cout + coA) * HW + P0;
            const float* pl8 = pl0 + (size_t)8 * HW;
            #pragma unroll
            for (int nf = 0; nf < 8; nf++) {
                int np = nwoff + nf * 8 + 2 * k4;
                float d0 = fmaxf(acc[f][nf][0] + bv0, 0.0f) - pl0[np];
                float d1 = fmaxf(acc[f][nf][1] + bv0, 0.0f) - pl0[np + 1];
                float d2 = fmaxf(acc[f][nf][2] + bv8, 0.0f) - pl8[np];
                float d3 = fmaxf(acc[f][nf][3] + bv8, 0.0f) - pl8[np + 1];
                lsum = fmaf(d0, d0, lsum);
                lsum = fmaf(d1, d1, lsum);
                lsum = fmaf(d2, d2, lsum);
                lsum = fmaf(d3, d3, lsum);
            }
        }
        float tot = block_reduce_sum(lsum, s_red, tid);
        if (tid == 0) atomicAdd(&g_acc[2], (double)tot);
    }
}

// ---------------- finalize ----------------
__global__ void finalize_kernel(float* out, int out_size) {
    double mse    = g_acc[0] / 524288.0;                 // 8*1*256*256
    double ssim_l = 1.0 - g_acc[1] / 500000.0;           // 8*250*250
    double perc   = g_acc[2] / 33554432.0;               // 8*256*128*128
    double total  = mse + 0.5 * ssim_l + 0.1 * perc;
    float vals[4] = {(float)total, (float)mse, (float)ssim_l, (float)perc};
    for (int i = 0; i < 4 && i < out_size; i++) out[i] = vals[i];
}

// ---------------- launcher ----------------
extern "C" void kernel_launch(void* const* d_in, const int* in_sizes, int n_in,
                              void* d_out, int out_size) {
    (void)in_sizes; (void)n_in;
    const float* sr = (const float*)d_in[0];
    const float* hr = (const float*)d_in[1];
    const float* w1 = (const float*)d_in[2];
    const float* b1 = (const float*)d_in[3];
    const float* w2 = (const float*)d_in[4];
    const float* b2 = (const float*)d_in[5];
    const float* w3 = (const float*)d_in[6];
    const float* b3 = (const float*)d_in[7];
    const float* w4 = (const float*)d_in[8];
    const float* b4 = (const float*)d_in[9];
    float* out = (float*)d_out;

    float *A, *B, *C, *D;
    cudaGetSymbolAddress((void**)&A, g_bufA);
    cudaGetSymbolAddress((void**)&B, g_bufB);
    cudaGetSymbolAddress((void**)&C, g_bufC);
    cudaGetSymbolAddress((void**)&D, g_bufD);

    const int smem256 = (3 * 258 * 8 + 9 * 512) * 4;   // 43200 B
    const int smem128 = (4 * 130 * 8 + 9 * 512) * 4;   // 35072 B

    zero_acc_kernel<<<1, 1>>>();
    mse_kernel<<<512, 256>>>(sr, hr, 524288);
    ssim_kernel<<<dim3(16, 16, 8), dim3(16, 16)>>>(sr, hr);

    for (int pass = 0; pass < 2; pass++) {
        const float* img = pass ? hr : sr;
        // conv1: (8,1,256,256) -> A (8,64,256,256)
        conv1_kernel<<<512, 256>>>(img, w1, b1, A);
        // conv2: A -> B (8,128,256,256)
        conv_mma<256><<<dim3(256, 2, 8), 256, smem256>>>(A, w2, b2, B, nullptr, 64, 128, 0);
        // pool: B -> A (8,128,128,128)
        pool_kernel<<<8192, 256>>>(B, A, 128, 128, 128);
        // conv3: A -> C (8,256,128,128)
        conv_mma<128><<<dim3(64, 4, 8), 256, smem128>>>(A, w3, b3, C, nullptr, 128, 256, 0);
        // conv4: C -> D (store on sr pass) or diff-reduce vs D (hr pass)
        if (pass == 0)
            conv_mma<128><<<dim3(64, 4, 8), 256, smem128>>>(C, w4, b4, D, nullptr, 256, 256, 0);
        else
            conv_mma<128><<<dim3(64, 4, 8), 256, smem128>>>(C, w4, b4, nullptr, D, 256, 256, 1);
    }

    finalize_kernel<<<1, 1>>>(out, out_size);
}

// round 5
// speedup vs baseline: 4.2911x; 1.0972x over previous
#include <cuda_runtime.h>
#include <math.h>

// ---------------- scratch (device globals; no allocation allowed) ----------
__device__ float g_bufA[33554432];   // conv1 out (8,64,256,256) / pooled (8,128,128,128)
__device__ float g_bufB[67108864];   // conv2 out (8,128,256,256)
__device__ float g_bufC[33554432];   // conv3 out (8,256,128,128)
__device__ float g_bufD[33554432];   // conv4 out for sr pass (8,256,128,128)
__device__ float g_wpk[1048576];     // packed tf32 weights (conv2|conv3|conv4)
__device__ double g_acc[3];          // 0: mse sum, 1: ssim S sum, 2: perceptual sum

__global__ void zero_acc_kernel() {
    g_acc[0] = 0.0; g_acc[1] = 0.0; g_acc[2] = 0.0;
}

// ---------------- helpers ----------------
__device__ __forceinline__ float block_reduce_sum(float v, float* sh, int tid) {
    #pragma unroll
    for (int o = 16; o > 0; o >>= 1) v += __shfl_down_sync(0xffffffffu, v, o);
    if ((tid & 31) == 0) sh[tid >> 5] = v;
    __syncthreads();
    if (tid < 32) {
        v = (tid < 8) ? sh[tid] : 0.0f;   // 256 threads -> 8 warps
        #pragma unroll
        for (int o = 4; o > 0; o >>= 1) v += __shfl_down_sync(0xffffffffu, v, o);
    }
    return v;  // valid in tid 0
}

__device__ __forceinline__ float to_tf32(float x) {
    asm("cvt.rna.tf32.f32 %0, %0;" : "+f"(x));
    return x;
}

__device__ __forceinline__ void mma_tf32(float* c, const float4 a, const float2 b) {
    asm volatile(
        "mma.sync.aligned.m16n8k8.row.col.f32.tf32.tf32.f32 "
        "{%0,%1,%2,%3}, {%4,%5,%6,%7}, {%8,%9}, {%0,%1,%2,%3};"
        : "+f"(c[0]), "+f"(c[1]), "+f"(c[2]), "+f"(c[3])
        : "r"(__float_as_uint(a.x)), "r"(__float_as_uint(a.y)),
          "r"(__float_as_uint(a.z)), "r"(__float_as_uint(a.w)),
          "r"(__float_as_uint(b.x)), "r"(__float_as_uint(b.y)));
}

__device__ __forceinline__ void cp_async4(unsigned dst, const void* src, bool ok) {
    int sz = ok ? 4 : 0;
    asm volatile("cp.async.ca.shared.global [%0], [%1], 4, %2;"
                 :: "r"(dst), "l"(src), "r"(sz));
}
__device__ __forceinline__ void cp_async16(unsigned dst, const void* src) {
    asm volatile("cp.async.cg.shared.global [%0], [%1], 16;" :: "r"(dst), "l"(src));
}
__device__ __forceinline__ void cp_commit() {
    asm volatile("cp.async.commit_group;");
}
template<int N>
__device__ __forceinline__ void cp_wait() {
    asm volatile("cp.async.wait_group %0;" :: "n"(N));
}

// ---------------- MSE ----------------
__global__ void mse_kernel(const float* __restrict__ a, const float* __restrict__ b, int n) {
    __shared__ float sh[32];
    float s = 0.0f;
    for (int i = blockIdx.x * blockDim.x + threadIdx.x; i < n; i += gridDim.x * blockDim.x) {
        float d = a[i] - b[i];
        s = fmaf(d, d, s);
    }
    s = block_reduce_sum(s, sh, threadIdx.x);
    if (threadIdx.x == 0) atomicAdd(&g_acc[0], (double)s);
}

// ---------------- SSIM (7x7 valid box filter, skimage formula) -------------
__global__ void ssim_kernel(const float* __restrict__ x, const float* __restrict__ y) {
    __shared__ float sxt[22][23];
    __shared__ float syt[22][23];
    __shared__ float sh[32];
    int b = blockIdx.z;
    int gx0 = blockIdx.x * 16, gy0 = blockIdx.y * 16;
    const float* xb = x + (size_t)b * 65536;
    const float* yb = y + (size_t)b * 65536;
    int tid = threadIdx.y * 16 + threadIdx.x;
    for (int i = tid; i < 22 * 22; i += 256) {
        int rr = i / 22, cc = i - rr * 22;
        int gy = gy0 + rr, gx = gx0 + cc;
        float vx = 0.0f, vy = 0.0f;
        if (gy < 256 && gx < 256) { vx = xb[gy * 256 + gx]; vy = yb[gy * 256 + gx]; }
        sxt[rr][cc] = vx; syt[rr][cc] = vy;
    }
    __syncthreads();
    int i = gy0 + threadIdx.y, j = gx0 + threadIdx.x;
    float S = 0.0f;
    if (i < 250 && j < 250) {
        float sx = 0, sy = 0, sxx = 0, syy = 0, sxy = 0;
        #pragma unroll
        for (int dy = 0; dy < 7; dy++) {
            #pragma unroll
            for (int dx = 0; dx < 7; dx++) {
                float a = sxt[threadIdx.y + dy][threadIdx.x + dx];
                float c = syt[threadIdx.y + dy][threadIdx.x + dx];
                sx += a; sy += c;
                sxx = fmaf(a, a, sxx); syy = fmaf(c, c, syy); sxy = fmaf(a, c, sxy);
            }
        }
        const float inv = 1.0f / 49.0f;
        const float cn  = 49.0f / 48.0f;
        float ux = sx * inv, uy = sy * inv;
        float vx  = cn * (sxx * inv - ux * ux);
        float vy  = cn * (syy * inv - uy * uy);
        float vxy = cn * (sxy * inv - ux * uy);
        const float C1 = 1e-4f, C2 = 9e-4f;
        S = ((2.0f * ux * uy + C1) * (2.0f * vxy + C2)) /
            ((ux * ux + uy * uy + C1) * (vx + vy + C2));
    }
    float tot = block_reduce_sum(S, sh, tid);
    if (tid == 0) atomicAdd(&g_acc[1], (double)tot);
}

// ---------------- conv1: 1 -> 64 channels, 256x256 SAME, relu --------------
// Output rounded to tf32 (it is only consumed by the tf32 conv2).
__global__ void conv1_kernel(const float* __restrict__ in, const float* __restrict__ w,
                             const float* __restrict__ bias, float* __restrict__ out) {
    __shared__ float sw[576];
    __shared__ float sb[64];
    int tid = threadIdx.x;
    for (int i = tid; i < 576; i += 256) sw[i] = w[i];
    if (tid < 64) sb[tid] = bias[tid];
    __syncthreads();
    int g = blockIdx.x * 256 + tid;
    int x4 = (g & 63) * 4;
    int y  = (g >> 6) & 255;
    int b  = g >> 14;
    const float* ib = in + (size_t)b * 65536;
    float inp[3][6];
    #pragma unroll
    for (int dy = 0; dy < 3; dy++) {
        int gy = y - 1 + dy;
        #pragma unroll
        for (int c = 0; c < 6; c++) {
            int gx = x4 - 1 + c;
            inp[dy][c] = ((unsigned)gy < 256u && (unsigned)gx < 256u) ? ib[gy * 256 + gx] : 0.0f;
        }
    }
    for (int co = 0; co < 64; co++) {
        float bv = sb[co];
        float a0 = bv, a1 = bv, a2 = bv, a3 = bv;
        #pragma unroll
        for (int k = 0; k < 9; k++) {
            float wv = sw[co * 9 + k];
            int ky = k / 3, kx = k - ky * 3;
            a0 = fmaf(inp[ky][0 + kx], wv, a0);
            a1 = fmaf(inp[ky][1 + kx], wv, a1);
            a2 = fmaf(inp[ky][2 + kx], wv, a2);
            a3 = fmaf(inp[ky][3 + kx], wv, a3);
        }
        float4 v = make_float4(to_tf32(fmaxf(a0, 0.0f)), to_tf32(fmaxf(a1, 0.0f)),
                               to_tf32(fmaxf(a2, 0.0f)), to_tf32(fmaxf(a3, 0.0f)));
        *(float4*)(out + ((size_t)(b * 64 + co) * 65536) + (size_t)y * 256 + x4) = v;
    }
}

// ---------------- maxpool 2x2 stride 2 ----------------
__global__ void pool_kernel(const float* __restrict__ in, float* __restrict__ out,
                            int C, int Ho, int Wo) {
    int n = 8 * C * Ho * Wo;
    int Wi = 2 * Wo;
    for (int i = blockIdx.x * blockDim.x + threadIdx.x; i < n; i += gridDim.x * blockDim.x) {
        int x = i % Wo;
        int y = (i / Wo) % Ho;
        int bc = i / (Wo * Ho);
        const float* p = in + ((size_t)bc * 2 * Ho + 2 * y) * Wi + 2 * x;
        float m = fmaxf(fmaxf(p[0], p[1]), fmaxf(p[Wi], p[Wi + 1]));
        out[i] = m;
    }
}

// ---------------- weight pre-pack: fragment-major tf32 ----------------
__global__ void pack_w_kernel(const float* __restrict__ w, float* __restrict__ dst,
                              int Cin, int Cout) {
    int total = (Cout / 64) * (Cin / 8) * 4608;
    for (int idx = blockIdx.x * blockDim.x + threadIdx.x; idx < total;
         idx += gridDim.x * blockDim.x) {
        int i    = idx & 511;
        int tap  = (idx >> 9) % 9;
        int rest = idx / 4608;
        int step = rest % (Cin / 8);
        int cb   = rest / (Cin / 8);
        int e  = i & 3;
        int kk = (i >> 2) & 3;
        int qq = (i >> 4) & 7;
        int ff = (i >> 7) & 1;
        int mm = (i >> 8) & 1;
        int co = cb * 64 + mm * 32 + ff * 16 + qq + (e & 1) * 8;
        int ci = step * 8 + kk + (e >> 1) * 4;
        dst[idx] = to_tf32(w[((size_t)co * Cin + ci) * 9 + tap]);
    }
}

// ---------------- tensor-core 3x3 SAME conv (tf32 mma.sync), v3 ------------
// cp.async double-buffered pipeline; weights streamed from packed layout;
// activations are tf32 at rest (rounded by producers), staged raw.
template<int W>
__global__ __launch_bounds__(256, 2) void conv_mma(
    const float* __restrict__ in, const float* __restrict__ wpack,
    const float* __restrict__ bias,
    float* __restrict__ out, const float* __restrict__ ref,
    int Cin, int Cout, int mode)
{
    constexpr int H = W;
    constexpr int HW = W * W;
    constexpr int LW = (W == 256) ? 8 : 7;
    constexpr int NROWS = 256 / W;
    constexpr int SROWS = NROWS + 2;
    constexpr int SCOLS = W + 2;
    constexpr int NPIX  = SROWS * SCOLS;
    constexpr int SIN_FLOATS = NPIX * 8;
    constexpr int SW_FLOATS  = 9 * 512;

    extern __shared__ float smem[];
    float* s_in = smem;                          // 2 buffers
    float* s_w  = smem + 2 * SIN_FLOATS;         // 2 buffers
    __shared__ float s_red[32];

    int tid = threadIdx.x;
    int warp = tid >> 5;
    int lane = tid & 31;
    int q  = lane >> 2;
    int k4 = lane & 3;
    int mw = warp & 1;
    int nw = warp >> 1;
    int mwoff = mw * 32;
    int nwoff = nw * 64;

    int P0  = blockIdx.x * 256;
    int cb  = blockIdx.y;
    int co0 = cb * 64;
    int b   = blockIdx.z;
    int y0  = P0 >> LW;
    int steps = Cin >> 3;

    unsigned s_in_u = (unsigned)__cvta_generic_to_shared(s_in);
    unsigned s_w_u  = (unsigned)__cvta_generic_to_shared(s_w);

    int awb0 = (((mw * 2 + 0) * 8 + q) * 4 + k4) * 4;
    int awb1 = awb0 + 128;

    int bb[8];
    #pragma unroll
    for (int nf = 0; nf < 8; nf++) {
        int base = nwoff + nf * 8;
        int ry   = base >> LW;
        int col  = base & (W - 1);
        bb[nf] = (ry * SCOLS + col + q) * 8 + k4 * 2;
    }

    float acc[2][8][4];
    #pragma unroll
    for (int f = 0; f < 2; f++)
        #pragma unroll
        for (int nf = 0; nf < 8; nf++)
            #pragma unroll
            for (int e = 0; e < 4; e++) acc[f][nf][e] = 0.0f;

    const float* inb = in + (size_t)b * Cin * HW;
    const float* wblk = wpack + (size_t)cb * steps * 4608;

    // ---- staging (cp.async) ----
    auto stage = [&](int step, int buf) {
        int ci0 = step * 8;
        unsigned ibase = s_in_u + buf * SIN_FLOATS * 4;
        #pragma unroll 4
        for (int i = tid; i < NPIX * 8; i += 256) {
            int p = i >> 3;
            int j = i & 7;
            int kq = j >> 1;     // 0..3
            int hf = j & 1;      // 0/1 -> plane kq or kq+4
            int r = p / SCOLS, c = p - r * SCOLS;
            int gy = y0 - 1 + r;
            int gx = c - 1;
            bool ok = ((unsigned)gy < (unsigned)H) && ((unsigned)gx < (unsigned)W);
            const float* src = inb + (size_t)(ci0 + kq + hf * 4) * HW
                                   + (ok ? (gy * W + gx) : 0);
            cp_async4(ibase + (unsigned)(p * 8 + kq * 2 + hf) * 4, src, ok);
        }
        unsigned wbase = s_w_u + buf * SW_FLOATS * 4;
        const float* wsrc = wblk + (size_t)step * 4608;
        #pragma unroll
        for (int i = tid; i < 1152; i += 256)
            cp_async16(wbase + (unsigned)i * 16, wsrc + i * 4);
    };

    stage(0, 0);
    cp_commit();

    for (int s = 0; s < steps; s++) {
        int cur = s & 1;
        if (s + 1 < steps) {
            stage(s + 1, cur ^ 1);
            cp_commit();
            cp_wait<1>();
        } else {
            cp_wait<0>();
        }
        __syncthreads();

        const float* bin = s_in + cur * SIN_FLOATS;
        const float* bw  = s_w  + cur * SW_FLOATS;

        #pragma unroll
        for (int tap = 0; tap < 9; tap++) {
            const int ky = tap / 3, kx = tap - ky * 3;
            const int toff = (ky * SCOLS + kx) * 8;
            float4 af0 = *(const float4*)(bw + tap * 512 + awb0);
            float4 af1 = *(const float4*)(bw + tap * 512 + awb1);
            #pragma unroll
            for (int nf = 0; nf < 8; nf++) {
                float2 bv = *(const float2*)(bin + bb[nf] + toff);
                mma_tf32(acc[0][nf], af0, bv);
                mma_tf32(acc[1][nf], af1, bv);
            }
        }
        __syncthreads();
    }

    // ---- epilogue (outputs rounded to tf32 so downstream raw-staging is exact) ----
    if (mode == 0) {
        #pragma unroll
        for (int f = 0; f < 2; f++) {
            int coA = co0 + mwoff + f * 16 + q;
            float bv0 = __ldg(&bias[coA]);
            float bv8 = __ldg(&bias[coA + 8]);
            float* pl0 = out + (size_t)(b * Cout + coA) * HW + P0;
            float* pl8 = pl0 + (size_t)8 * HW;
            #pragma unroll
            for (int nf = 0; nf < 8; nf++) {
                int np = nwoff + nf * 8 + 2 * k4;
                float2 v0, v8;
                v0.x = to_tf32(fmaxf(acc[f][nf][0] + bv0, 0.0f));
                v0.y = to_tf32(fmaxf(acc[f][nf][1] + bv0, 0.0f));
                v8.x = to_tf32(fmaxf(acc[f][nf][2] + bv8, 0.0f));
                v8.y = to_tf32(fmaxf(acc[f][nf][3] + bv8, 0.0f));
                *(float2*)(pl0 + np) = v0;
                *(float2*)(pl8 + np) = v8;
            }
        }
    } else {
        float lsum = 0.0f;
        #pragma unroll
        for (int f = 0; f < 2; f++) {
            int coA = co0 + mwoff + f * 16 + q;
            float bv0 = __ldg(&bias[coA]);
            float bv8 = __ldg(&bias[coA + 8]);
            const float* pl0 = ref + (size_t)(b * Cout + coA) * HW + P0;
            const float* pl8 = pl0 + (size_t)8 * HW;
            #pragma unroll
            for (int nf = 0; nf < 8; nf++) {
                int np = nwoff + nf * 8 + 2 * k4;
                float d0 = to_tf32(fmaxf(acc[f][nf][0] + bv0, 0.0f)) - pl0[np];
                float d1 = to_tf32(fmaxf(acc[f][nf][1] + bv0, 0.0f)) - pl0[np + 1];
                float d2 = to_tf32(fmaxf(acc[f][nf][2] + bv8, 0.0f)) - pl8[np];
                float d3 = to_tf32(fmaxf(acc[f][nf][3] + bv8, 0.0f)) - pl8[np + 1];
                lsum = fmaf(d0, d0, lsum);
                lsum = fmaf(d1, d1, lsum);
                lsum = fmaf(d2, d2, lsum);
                lsum = fmaf(d3, d3, lsum);
            }
        }
        float tot = block_reduce_sum(lsum, s_red, tid);
        if (tid == 0) atomicAdd(&g_acc[2], (double)tot);
    }
}

// ---------------- finalize ----------------
__global__ void finalize_kernel(float* out, int out_size) {
    double mse    = g_acc[0] / 524288.0;                 // 8*1*256*256
    double ssim_l = 1.0 - g_acc[1] / 500000.0;           // 8*250*250
    double perc   = g_acc[2] / 33554432.0;               // 8*256*128*128
    double total  = mse + 0.5 * ssim_l + 0.1 * perc;
    float vals[4] = {(float)total, (float)mse, (float)ssim_l, (float)perc};
    for (int i = 0; i < 4 && i < out_size; i++) out[i] = vals[i];
}

// ---------------- launcher ----------------
extern "C" void kernel_launch(void* const* d_in, const int* in_sizes, int n_in,
                              void* d_out, int out_size) {
    (void)in_sizes; (void)n_in;
    const float* sr = (const float*)d_in[0];
    const float* hr = (const float*)d_in[1];
    const float* w1 = (const float*)d_in[2];
    const float* b1 = (const float*)d_in[3];
    const float* w2 = (const float*)d_in[4];
    const float* b2 = (const float*)d_in[5];
    const float* w3 = (const float*)d_in[6];
    const float* b3 = (const float*)d_in[7];
    const float* w4 = (const float*)d_in[8];
    const float* b4 = (const float*)d_in[9];
    float* out = (float*)d_out;

    float *A, *B, *C, *D, *WP;
    cudaGetSymbolAddress((void**)&A, g_bufA);
    cudaGetSymbolAddress((void**)&B, g_bufB);
    cudaGetSymbolAddress((void**)&C, g_bufC);
    cudaGetSymbolAddress((void**)&D, g_bufD);
    cudaGetSymbolAddress((void**)&WP, g_wpk);
    float* WP2 = WP;            // 73728 floats
    float* WP3 = WP + 73728;    // 294912 floats
    float* WP4 = WP + 368640;   // 589824 floats

    // smem: 2*input + 2*weights buffers
    const int smem256 = (2 * (3 * 258 * 8) + 2 * 4608) * 4;   // 86400 B
    const int smem128 = (2 * (4 * 130 * 8) + 2 * 4608) * 4;   // 70144 B
    cudaFuncSetAttribute(conv_mma<256>, cudaFuncAttributeMaxDynamicSharedMemorySize, smem256);
    cudaFuncSetAttribute(conv_mma<128>, cudaFuncAttributeMaxDynamicSharedMemorySize, smem128);

    zero_acc_kernel<<<1, 1>>>();
    // pack weights (tiny)
    pack_w_kernel<<<72, 256>>>(w2, WP2, 64, 128);
    pack_w_kernel<<<288, 256>>>(w3, WP3, 128, 256);
    pack_w_kernel<<<576, 256>>>(w4, WP4, 256, 256);

    mse_kernel<<<512, 256>>>(sr, hr, 524288);
    ssim_kernel<<<dim3(16, 16, 8), dim3(16, 16)>>>(sr, hr);

    for (int pass = 0; pass < 2; pass++) {
        const float* img = pass ? hr : sr;
        conv1_kernel<<<512, 256>>>(img, w1, b1, A);
        conv_mma<256><<<dim3(256, 2, 8), 256, smem256>>>(A, WP2, b2, B, nullptr, 64, 128, 0);
        pool_kernel<<<8192, 256>>>(B, A, 128, 128, 128);
        conv_mma<128><<<dim3(64, 4, 8), 256, smem128>>>(A, WP3, b3, C, nullptr, 128, 256, 0);
        if (pass == 0)
            conv_mma<128><<<dim3(64, 4, 8), 256, smem128>>>(C, WP4, b4, D, nullptr, 256, 256, 0);
        else
            conv_mma<128><<<dim3(64, 4, 8), 256, smem128>>>(C, WP4, b4, nullptr, D, 256, 256, 1);
    }

    finalize_kernel<<<1, 1>>>(out, out_size);
}

// round 6
// speedup vs baseline: 8.4001x; 1.9576x over previous
#include <cuda_runtime.h>
#include <cuda_bf16.h>
#include <math.h>

// ---------------- scratch (device globals; no allocation allowed) ----------
// Activations are bf16x2 "pair-planes": pair (ci, ci+8) within each 16-channel
// block; plane index pp = (ci/16)*8 + (ci%8). One uint32 per pixel per plane.
__device__ unsigned g_bufA[16777216];  // conv1 out (8,32pp,256,256) / pooled (8,64pp,128,128)
__device__ unsigned g_bufB[33554432];  // conv2 out (8,64pp,256,256)
__device__ unsigned g_bufC[16777216];  // conv3 out (8,128pp,128,128)
__device__ unsigned g_bufD[16777216];  // conv4 out sr pass (8,128pp,128,128)
__device__ unsigned g_wpk[524288];     // packed bf16 A-fragment weights
__device__ double g_acc[3];            // 0: mse, 1: ssim S sum, 2: perceptual

__global__ void zero_acc_kernel() {
    g_acc[0] = 0.0; g_acc[1] = 0.0; g_acc[2] = 0.0;
}

// ---------------- helpers ----------------
__device__ __forceinline__ float block_reduce_sum(float v, float* sh, int tid) {
    #pragma unroll
    for (int o = 16; o > 0; o >>= 1) v += __shfl_down_sync(0xffffffffu, v, o);
    if ((tid & 31) == 0) sh[tid >> 5] = v;
    __syncthreads();
    if (tid < 32) {
        v = (tid < 8) ? sh[tid] : 0.0f;
        #pragma unroll
        for (int o = 4; o > 0; o >>= 1) v += __shfl_down_sync(0xffffffffu, v, o);
    }
    return v;
}

__device__ __forceinline__ unsigned pack_bf2(float lo, float hi) {
    __nv_bfloat162 h = __floats2bfloat162_rn(lo, hi);
    return *(unsigned*)&h;
}
__device__ __forceinline__ float2 unpack_bf2(unsigned u) {
    __nv_bfloat162 h = *(__nv_bfloat162*)&u;
    return __bfloat1622float2(h);
}
__device__ __forceinline__ float bf16r(float x) {
    return __bfloat162float(__float2bfloat16_rn(x));
}

__device__ __forceinline__ void mma_bf16(float* c, const uint4 a, const uint2 b) {
    asm volatile(
        "mma.sync.aligned.m16n8k16.row.col.f32.bf16.bf16.f32 "
        "{%0,%1,%2,%3}, {%4,%5,%6,%7}, {%8,%9}, {%0,%1,%2,%3};"
        : "+f"(c[0]), "+f"(c[1]), "+f"(c[2]), "+f"(c[3])
        : "r"(a.x), "r"(a.y), "r"(a.z), "r"(a.w), "r"(b.x), "r"(b.y));
}

__device__ __forceinline__ void cp_async4(unsigned dst, const void* src, bool ok) {
    int sz = ok ? 4 : 0;
    asm volatile("cp.async.ca.shared.global [%0], [%1], 4, %2;"
                 :: "r"(dst), "l"(src), "r"(sz));
}
__device__ __forceinline__ void cp_async16(unsigned dst, const void* src) {
    asm volatile("cp.async.cg.shared.global [%0], [%1], 16;" :: "r"(dst), "l"(src));
}
__device__ __forceinline__ void cp_commit() {
    asm volatile("cp.async.commit_group;");
}
template<int N>
__device__ __forceinline__ void cp_wait() {
    asm volatile("cp.async.wait_group %0;" :: "n"(N));
}

// ---------------- MSE ----------------
__global__ void mse_kernel(const float* __restrict__ a, const float* __restrict__ b, int n) {
    __shared__ float sh[32];
    float s = 0.0f;
    for (int i = blockIdx.x * blockDim.x + threadIdx.x; i < n; i += gridDim.x * blockDim.x) {
        float d = a[i] - b[i];
        s = fmaf(d, d, s);
    }
    s = block_reduce_sum(s, sh, threadIdx.x);
    if (threadIdx.x == 0) atomicAdd(&g_acc[0], (double)s);
}

// ---------------- SSIM ----------------
__global__ void ssim_kernel(const float* __restrict__ x, const float* __restrict__ y) {
    __shared__ float sxt[22][23];
    __shared__ float syt[22][23];
    __shared__ float sh[32];
    int b = blockIdx.z;
    int gx0 = blockIdx.x * 16, gy0 = blockIdx.y * 16;
    const float* xb = x + (size_t)b * 65536;
    const float* yb = y + (size_t)b * 65536;
    int tid = threadIdx.y * 16 + threadIdx.x;
    for (int i = tid; i < 22 * 22; i += 256) {
        int rr = i / 22, cc = i - rr * 22;
        int gy = gy0 + rr, gx = gx0 + cc;
        float vx = 0.0f, vy = 0.0f;
        if (gy < 256 && gx < 256) { vx = xb[gy * 256 + gx]; vy = yb[gy * 256 + gx]; }
        sxt[rr][cc] = vx; syt[rr][cc] = vy;
    }
    __syncthreads();
    int i = gy0 + threadIdx.y, j = gx0 + threadIdx.x;
    float S = 0.0f;
    if (i < 250 && j < 250) {
        float sx = 0, sy = 0, sxx = 0, syy = 0, sxy = 0;
        #pragma unroll
        for (int dy = 0; dy < 7; dy++) {
            #pragma unroll
            for (int dx = 0; dx < 7; dx++) {
                float a = sxt[threadIdx.y + dy][threadIdx.x + dx];
                float c = syt[threadIdx.y + dy][threadIdx.x + dx];
                sx += a; sy += c;
                sxx = fmaf(a, a, sxx); syy = fmaf(c, c, syy); sxy = fmaf(a, c, sxy);
            }
        }
        const float inv = 1.0f / 49.0f;
        const float cn  = 49.0f / 48.0f;
        float ux = sx * inv, uy = sy * inv;
        float vx  = cn * (sxx * inv - ux * ux);
        float vy  = cn * (syy * inv - uy * uy);
        float vxy = cn * (sxy * inv - ux * uy);
        const float C1 = 1e-4f, C2 = 9e-4f;
        S = ((2.0f * ux * uy + C1) * (2.0f * vxy + C2)) /
            ((ux * ux + uy * uy + C1) * (vx + vy + C2));
    }
    float tot = block_reduce_sum(S, sh, tid);
    if (tid == 0) atomicAdd(&g_acc[1], (double)tot);
}

// ---------------- conv1: 1 -> 64 ch, relu, bf16 pair-plane output ----------
__global__ void conv1_kernel(const float* __restrict__ in, const float* __restrict__ w,
                             const float* __restrict__ bias, unsigned* __restrict__ out) {
    __shared__ float sw[576];
    __shared__ float sb[64];
    int tid = threadIdx.x;
    for (int i = tid; i < 576; i += 256) sw[i] = w[i];
    if (tid < 64) sb[tid] = bias[tid];
    __syncthreads();
    int g = blockIdx.x * 256 + tid;
    int x4 = (g & 63) * 4;
    int y  = (g >> 6) & 255;
    int b  = g >> 14;
    const float* ib = in + (size_t)b * 65536;
    float inp[3][6];
    #pragma unroll
    for (int dy = 0; dy < 3; dy++) {
        int gy = y - 1 + dy;
        #pragma unroll
        for (int c = 0; c < 6; c++) {
            int gx = x4 - 1 + c;
            inp[dy][c] = ((unsigned)gy < 256u && (unsigned)gx < 256u) ? ib[gy * 256 + gx] : 0.0f;
        }
    }
    for (int s = 0; s < 4; s++) {
        for (int c = 0; c < 8; c++) {
            int coL = 16 * s + c, coH = coL + 8;
            float al0 = sb[coL], al1 = al0, al2 = al0, al3 = al0;
            float ah0 = sb[coH], ah1 = ah0, ah2 = ah0, ah3 = ah0;
            #pragma unroll
            for (int k = 0; k < 9; k++) {
                int ky = k / 3, kx = k - ky * 3;
                float wl = sw[coL * 9 + k], wh = sw[coH * 9 + k];
                al0 = fmaf(inp[ky][0 + kx], wl, al0);
                al1 = fmaf(inp[ky][1 + kx], wl, al1);
                al2 = fmaf(inp[ky][2 + kx], wl, al2);
                al3 = fmaf(inp[ky][3 + kx], wl, al3);
                ah0 = fmaf(inp[ky][0 + kx], wh, ah0);
                ah1 = fmaf(inp[ky][1 + kx], wh, ah1);
                ah2 = fmaf(inp[ky][2 + kx], wh, ah2);
                ah3 = fmaf(inp[ky][3 + kx], wh, ah3);
            }
            uint4 v;
            v.x = pack_bf2(fmaxf(al0, 0.0f), fmaxf(ah0, 0.0f));
            v.y = pack_bf2(fmaxf(al1, 0.0f), fmaxf(ah1, 0.0f));
            v.z = pack_bf2(fmaxf(al2, 0.0f), fmaxf(ah2, 0.0f));
            v.w = pack_bf2(fmaxf(al3, 0.0f), fmaxf(ah3, 0.0f));
            *(uint4*)(out + ((size_t)(b * 32 + s * 8 + c) * 65536) + (size_t)y * 256 + x4) = v;
        }
    }
}

// ---------------- maxpool 2x2 on bf16x2 pair-planes ----------------
__global__ void pool_kernel(const unsigned* __restrict__ in, unsigned* __restrict__ out,
                            int PP, int Ho, int Wo) {
    int n = 8 * PP * Ho * Wo;
    int Wi = 2 * Wo;
    for (int i = blockIdx.x * blockDim.x + threadIdx.x; i < n; i += gridDim.x * blockDim.x) {
        int x = i % Wo;
        int y = (i / Wo) % Ho;
        int bc = i / (Wo * Ho);
        const unsigned* p = in + ((size_t)bc * 2 * Ho + 2 * y) * Wi + 2 * x;
        __nv_bfloat162 a = *(__nv_bfloat162*)&p[0];
        __nv_bfloat162 b = *(__nv_bfloat162*)&p[1];
        __nv_bfloat162 c = *(__nv_bfloat162*)&p[Wi];
        __nv_bfloat162 d = *(__nv_bfloat162*)&p[Wi + 1];
        __nv_bfloat162 m = __hmax2(__hmax2(a, b), __hmax2(c, d));
        out[i] = *(unsigned*)&m;
    }
}

// ---------------- weight pre-pack: bf16 m16n8k16 A-fragments ----------------
// idx within 512-u32 tap block: ((mw*2+f)*8+q)*16 + k4*4 + reg
// reg r: row = q + (r&1)*8 ; c = k4 + (r>>1)*4 ; ci_lo = step*16+c, ci_hi = +8
__global__ void pack_w_kernel(const float* __restrict__ w, unsigned* __restrict__ dst,
                              int Cin, int Cout) {
    int steps = Cin >> 4;
    int total = (Cout / 64) * steps * 4608;
    for (int idx = blockIdx.x * blockDim.x + threadIdx.x; idx < total;
         idx += gridDim.x * blockDim.x) {
        int reg = idx & 3;
        int k4  = (idx >> 2) & 3;
        int q   = (idx >> 4) & 7;
        int f   = (idx >> 7) & 1;
        int mw  = (idx >> 8) & 1;
        int tap = (idx >> 9) % 9;
        int rest = idx / 4608;
        int step = rest % steps;
        int cb   = rest / steps;
        int co = cb * 64 + mw * 32 + f * 16 + q + (reg & 1) * 8;
        int c  = k4 + (reg >> 1) * 4;
        int ci_lo = step * 16 + c;
        float lo = w[((size_t)co * Cin + ci_lo) * 9 + tap];
        float hi = w[((size_t)co * Cin + ci_lo + 8) * 9 + tap];
        dst[idx] = pack_bf2(lo, hi);
    }
}

// ---------------- tensor-core 3x3 SAME conv (bf16 m16n8k16) ----------------
// Block: 8 warps = 2(M:co) x 4(N:px). Block tile 64co x 256px; K=16 ci/step.
// SMEM input: [pixel][8 u32] ; in-pixel slot perm (c&3)*2+(c>>2) so the
// B fragment (units c=k4, c=k4+4) is one LDS.64.
template<int W>
__global__ __launch_bounds__(256, 2) void conv_mma(
    const unsigned* __restrict__ in, const unsigned* __restrict__ wpack,
    const float* __restrict__ bias,
    unsigned* __restrict__ out, const unsigned* __restrict__ ref,
    int Cin, int Cout, int mode)
{
    constexpr int H = W;
    constexpr int HW = W * W;
    constexpr int LW = (W == 256) ? 8 : 7;
    constexpr int NROWS = 256 / W;
    constexpr int SROWS = NROWS + 2;
    constexpr int SCOLS = W + 2;
    constexpr int NPIX  = SROWS * SCOLS;
    constexpr int SIN_U = NPIX * 8;          // u32 per input buffer
    constexpr int SW_U  = 9 * 512;           // u32 per weight buffer

    extern __shared__ unsigned smem_u[];
    unsigned* s_in = smem_u;                 // 2 buffers
    unsigned* s_w  = smem_u + 2 * SIN_U;     // 2 buffers
    __shared__ float s_red[32];

    int tid = threadIdx.x;
    int warp = tid >> 5;
    int lane = tid & 31;
    int q  = lane >> 2;
    int k4 = lane & 3;
    int mw = warp & 1;
    int nw = warp >> 1;
    int mwoff = mw * 32;
    int nwoff = nw * 64;

    int P0  = blockIdx.x * 256;
    int cb  = blockIdx.y;
    int co0 = cb * 64;
    int b   = blockIdx.z;
    int y0  = P0 >> LW;
    int steps = Cin >> 4;

    unsigned s_in_u = (unsigned)__cvta_generic_to_shared(s_in);
    unsigned s_w_u  = (unsigned)__cvta_generic_to_shared(s_w);

    int awb0 = ((mw * 2 + 0) * 8 + q) * 16 + k4 * 4;   // u32 offset
    int awb1 = awb0 + 128;                             // f=1

    int bb[8];
    #pragma unroll
    for (int nf = 0; nf < 8; nf++) {
        int base = nwoff + nf * 8;
        int ry   = base >> LW;
        int col  = base & (W - 1);
        bb[nf] = ((ry * SCOLS + col) + q) * 8 + 2 * k4;
    }

    float acc[2][8][4];
    #pragma unroll
    for (int f = 0; f < 2; f++)
        #pragma unroll
        for (int nf = 0; nf < 8; nf++)
            #pragma unroll
            for (int e = 0; e < 4; e++) acc[f][nf][e] = 0.0f;

    const unsigned* inb = in + (size_t)b * (Cin >> 1) * HW;
    const unsigned* wblk = wpack + (size_t)cb * steps * 4608;

    auto stage = [&](int step, int buf) {
        const unsigned* pbase = inb + (size_t)step * 8 * HW;
        unsigned ibase = s_in_u + buf * SIN_U * 4;
        #pragma unroll 4
        for (int i = tid; i < NPIX * 8; i += 256) {
            int p = i >> 3;
            int c = i & 7;
            int r = p / SCOLS, cc = p - r * SCOLS;
            int gy = y0 - 1 + r;
            int gx = cc - 1;
            bool ok = ((unsigned)gy < (unsigned)H) && ((unsigned)gx < (unsigned)W);
            const unsigned* src = pbase + (size_t)c * HW + (ok ? (gy * W + gx) : 0);
            int slot = ((c & 3) << 1) + (c >> 2);
            cp_async4(ibase + (unsigned)(p * 8 + slot) * 4, src, ok);
        }
        unsigned wbase = s_w_u + buf * SW_U * 4;
        const unsigned* wsrc = wblk + (size_t)step * 4608;
        #pragma unroll
        for (int i = tid; i < 1152; i += 256)
            cp_async16(wbase + (unsigned)i * 16, wsrc + i * 4);
    };

    stage(0, 0);
    cp_commit();

    for (int s = 0; s < steps; s++) {
        int cur = s & 1;
        if (s + 1 < steps) {
            stage(s + 1, cur ^ 1);
            cp_commit();
            cp_wait<1>();
        } else {
            cp_wait<0>();
        }
        __syncthreads();

        const unsigned* bin = s_in + cur * SIN_U;
        const unsigned* bw  = s_w  + cur * SW_U;

        #pragma unroll
        for (int tap = 0; tap < 9; tap++) {
            const int ky = tap / 3, kx = tap - ky * 3;
            const int toff = (ky * SCOLS + kx) * 8;
            uint4 af0 = *(const uint4*)(bw + tap * 512 + awb0);
            uint4 af1 = *(const uint4*)(bw + tap * 512 + awb1);
            #pragma unroll
            for (int nf = 0; nf < 8; nf++) {
                uint2 bv = *(const uint2*)(bin + bb[nf] + toff);
                mma_bf16(acc[0][nf], af0, bv);
                mma_bf16(acc[1][nf], af1, bv);
            }
        }
        __syncthreads();
    }

    // ---- epilogue: pair-plane bf16 outputs ----
    if (mode == 0) {
        #pragma unroll
        for (int f = 0; f < 2; f++) {
            int coL = co0 + mwoff + f * 16 + q;
            float bv0 = __ldg(&bias[coL]);
            float bv8 = __ldg(&bias[coL + 8]);
            int pp = ((co0 + mwoff + f * 16) >> 4) * 8 + q;
            unsigned* pl = out + (size_t)(b * (Cout >> 1) + pp) * HW + P0;
            #pragma unroll
            for (int nf = 0; nf < 8; nf++) {
                int np = nwoff + nf * 8 + 2 * k4;
                uint2 v;
                v.x = pack_bf2(fmaxf(acc[f][nf][0] + bv0, 0.0f),
                               fmaxf(acc[f][nf][2] + bv8, 0.0f));
                v.y = pack_bf2(fmaxf(acc[f][nf][1] + bv0, 0.0f),
                               fmaxf(acc[f][nf][3] + bv8, 0.0f));
                *(uint2*)(pl + np) = v;
            }
        }
    } else {
        float lsum = 0.0f;
        #pragma unroll
        for (int f = 0; f < 2; f++) {
            int coL = co0 + mwoff + f * 16 + q;
            float bv0 = __ldg(&bias[coL]);
            float bv8 = __ldg(&bias[coL + 8]);
            int pp = ((co0 + mwoff + f * 16) >> 4) * 8 + q;
            const unsigned* pl = ref + (size_t)(b * (Cout >> 1) + pp) * HW + P0;
            #pragma unroll
            for (int nf = 0; nf < 8; nf++) {
                int np = nwoff + nf * 8 + 2 * k4;
                uint2 rv = *(const uint2*)(pl + np);
                float2 r0 = unpack_bf2(rv.x);
                float2 r1 = unpack_bf2(rv.y);
                float d0 = bf16r(fmaxf(acc[f][nf][0] + bv0, 0.0f)) - r0.x;
                float d1 = bf16r(fmaxf(acc[f][nf][2] + bv8, 0.0f)) - r0.y;
                float d2 = bf16r(fmaxf(acc[f][nf][1] + bv0, 0.0f)) - r1.x;
                float d3 = bf16r(fmaxf(acc[f][nf][3] + bv8, 0.0f)) - r1.y;
                lsum = fmaf(d0, d0, lsum);
                lsum = fmaf(d1, d1, lsum);
                lsum = fmaf(d2, d2, lsum);
                lsum = fmaf(d3, d3, lsum);
            }
        }
        float tot = block_reduce_sum(lsum, s_red, tid);
        if (tid == 0) atomicAdd(&g_acc[2], (double)tot);
    }
}

// ---------------- finalize ----------------
__global__ void finalize_kernel(float* out, int out_size) {
    double mse    = g_acc[0] / 524288.0;
    double ssim_l = 1.0 - g_acc[1] / 500000.0;
    double perc   = g_acc[2] / 33554432.0;
    double total  = mse + 0.5 * ssim_l + 0.1 * perc;
    float vals[4] = {(float)total, (float)mse, (float)ssim_l, (float)perc};
    for (int i = 0; i < 4 && i < out_size; i++) out[i] = vals[i];
}

// ---------------- launcher ----------------
extern "C" void kernel_launch(void* const* d_in, const int* in_sizes, int n_in,
                              void* d_out, int out_size) {
    (void)in_sizes; (void)n_in;
    const float* sr = (const float*)d_in[0];
    const float* hr = (const float*)d_in[1];
    const float* w1 = (const float*)d_in[2];
    const float* b1 = (const float*)d_in[3];
    const float* w2 = (const float*)d_in[4];
    const float* b2 = (const float*)d_in[5];
    const float* w3 = (const float*)d_in[6];
    const float* b3 = (const float*)d_in[7];
    const float* w4 = (const float*)d_in[8];
    const float* b4 = (const float*)d_in[9];
    float* out = (float*)d_out;

    unsigned *A, *B, *C, *D, *WP;
    cudaGetSymbolAddress((void**)&A, g_bufA);
    cudaGetSymbolAddress((void**)&B, g_bufB);
    cudaGetSymbolAddress((void**)&C, g_bufC);
    cudaGetSymbolAddress((void**)&D, g_bufD);
    cudaGetSymbolAddress((void**)&WP, g_wpk);
    unsigned* WP2 = WP;             // 2*4*4608  = 36864 u32
    unsigned* WP3 = WP + 36864;     // 4*8*4608  = 147456 u32
    unsigned* WP4 = WP + 184320;    // 4*16*4608 = 294912 u32

    const int smem256 = (2 * (3 * 258 * 8) + 2 * 4608) * 4;   // 86400 B
    const int smem128 = (2 * (4 * 130 * 8) + 2 * 4608) * 4;   // 70144 B
    cudaFuncSetAttribute(conv_mma<256>, cudaFuncAttributeMaxDynamicSharedMemorySize, smem256);
    cudaFuncSetAttribute(conv_mma<128>, cudaFuncAttributeMaxDynamicSharedMemorySize, smem128);

    zero_acc_kernel<<<1, 1>>>();
    pack_w_kernel<<<144, 256>>>(w2, WP2, 64, 128);
    pack_w_kernel<<<576, 256>>>(w3, WP3, 128, 256);
    pack_w_kernel<<<1152, 256>>>(w4, WP4, 256, 256);

    mse_kernel<<<512, 256>>>(sr, hr, 524288);
    ssim_kernel<<<dim3(16, 16, 8), dim3(16, 16)>>>(sr, hr);

    for (int pass = 0; pass < 2; pass++) {
        const float* img = pass ? hr : sr;
        conv1_kernel<<<512, 256>>>(img, w1, b1, A);
        conv_mma<256><<<dim3(256, 2, 8), 256, smem256>>>(A, WP2, b2, B, nullptr, 64, 128, 0);
        pool_kernel<<<4096, 256>>>(B, A, 64, 128, 128);
        conv_mma<128><<<dim3(64, 4, 8), 256, smem128>>>(A, WP3, b3, C, nullptr, 128, 256, 0);
        if (pass == 0)
            conv_mma<128><<<dim3(64, 4, 8), 256, smem128>>>(C, WP4, b4, D, nullptr, 256, 256, 0);
        else
            conv_mma<128><<<dim3(64, 4, 8), 256, smem128>>>(C, WP4, b4, nullptr, D, 256, 256, 1);
    }

    finalize_kernel<<<1, 1>>>(out, out_size);
}